// round 16
// baseline (speedup 1.0000x reference)
#include <cuda_runtime.h>
#include <cuda_bf16.h>
#include <cuda_fp16.h>
#include <math.h>

#define N_NODES 30000
#define F_IN    256
#define N_EDGES 300000
#define HEADS   8
#define CDIM    128
#define HC      1024
#define OUTD    64
#define NEG_SLOPE 0.2f

// ---------------- scratch ----------------
__device__ __align__(256) __half d_h1h  [(size_t)N_NODES * HC];  // 61.4 MB
__device__ __align__(256) __half d_agg1h[(size_t)N_NODES * HC];  // 61.4 MB
__device__ __align__(256) __half d_xh   [(size_t)N_NODES * F_IN]; // 15.4 MB
__device__ __align__(256) __half d_w1h  [F_IN * HC];              // W1 fp16
__device__ __align__(256) __half d_w2h  [HC * OUTD];              // W2 hi fp16
__device__ __align__(256) __half d_w2l  [HC * OUTD];              // W2 lo fp16
__device__ __align__(256) float  d_asrc1[N_NODES * HEADS];
__device__ __align__(256) float  d_adst1[N_NODES * HEADS];
__device__ __align__(256) float  d_h2  [(size_t)N_NODES * OUTD];
__device__ __align__(256) float  d_asrc2[N_NODES];
__device__ __align__(256) float  d_adst2[N_NODES];
__device__ __align__(256) int    d_deg   [N_NODES];
__device__ __align__(256) int    d_rowptr[N_NODES + 1];
__device__ __align__(256) int    d_cursor[N_NODES];
__device__ __align__(256) int    d_csr_src[N_EDGES];

// ---------------- helpers ----------------
__device__ __forceinline__ float lrelu(float x) { return x > 0.f ? x : NEG_SLOPE * x; }

__device__ __forceinline__ unsigned smem_u32(const void* p) {
    unsigned a;
    asm("{ .reg .u64 t; cvta.to.shared.u64 t, %1; cvt.u32.u64 %0, t; }" : "=r"(a) : "l"(p));
    return a;
}

__device__ __forceinline__ void split2h(float x, float y, unsigned& h, unsigned& l) {
    __half hx = __float2half_rn(x);
    __half hy = __float2half_rn(y);
    float rx = x - __half2float(hx);
    float ry = y - __half2float(hy);
    __half lx = __float2half_rn(rx);
    __half ly = __float2half_rn(ry);
    h = (unsigned)__half_as_ushort(hx) | ((unsigned)__half_as_ushort(hy) << 16);
    l = (unsigned)__half_as_ushort(lx) | ((unsigned)__half_as_ushort(ly) << 16);
}

__device__ __forceinline__ void mma_f16(float* c, const unsigned* a, unsigned b0, unsigned b1) {
    asm volatile("mma.sync.aligned.m16n8k16.row.col.f32.f16.f16.f32 "
                 "{%0,%1,%2,%3}, {%4,%5,%6,%7}, {%8,%9}, {%0,%1,%2,%3};\n"
                 : "+f"(c[0]), "+f"(c[1]), "+f"(c[2]), "+f"(c[3])
                 : "r"(a[0]), "r"(a[1]), "r"(a[2]), "r"(a[3]), "r"(b0), "r"(b1));
}

__device__ __forceinline__ void ldsm_x4(unsigned& r0, unsigned& r1, unsigned& r2, unsigned& r3, unsigned a) {
    asm volatile("ldmatrix.sync.aligned.m8n8.x4.shared.b16 {%0,%1,%2,%3}, [%4];"
                 : "=r"(r0), "=r"(r1), "=r"(r2), "=r"(r3) : "r"(a));
}
__device__ __forceinline__ void ldsm_x4_t(unsigned& r0, unsigned& r1, unsigned& r2, unsigned& r3, unsigned a) {
    asm volatile("ldmatrix.sync.aligned.m8n8.x4.trans.shared.b16 {%0,%1,%2,%3}, [%4];"
                 : "=r"(r0), "=r"(r1), "=r"(r2), "=r"(r3) : "r"(a));
}

#define CPA16(dst, src, sz) \
    asm volatile("cp.async.cg.shared.global [%0], [%1], 16, %2;\n" :: "r"(dst), "l"(src), "r"(sz))

// L2 evict-last access policy (created once per thread), applied via cache_hint loads
__device__ __forceinline__ unsigned long long mk_policy_el() {
    unsigned long long pol;
    asm("createpolicy.fractional.L2::evict_last.b64 %0, 1.0;" : "=l"(pol));
    return pol;
}
__device__ __forceinline__ uint2 ldg_el(const __half* p, unsigned long long pol) {
    uint2 r;
    asm volatile("ld.global.L2::cache_hint.v2.u32 {%0,%1}, [%2], %3;"
                 : "=r"(r.x), "=r"(r.y) : "l"(p), "l"(pol));
    return r;
}
__device__ __forceinline__ void acc_h4_el(float4& acc, const __half* base, float w, unsigned long long pol) {
    uint2 raw = ldg_el(base, pol);
    float2 u0 = __half22float2(*reinterpret_cast<const __half2*>(&raw.x));
    float2 u1 = __half22float2(*reinterpret_cast<const __half2*>(&raw.y));
    acc.x += w * u0.x; acc.y += w * u0.y; acc.z += w * u1.x; acc.w += w * u1.y;
}

// ---------------- conversion kernels ----------------
__global__ void convx_k(const float* __restrict__ x)
{
    int i = blockIdx.x * 256 + threadIdx.x;
    if (i >= N_NODES * F_IN / 4) return;
    float4 v = ((const float4*)x)[i];
    __half2 h0 = __floats2half2_rn(v.x, v.y), h1 = __floats2half2_rn(v.z, v.w);
    uint2 o;
    o.x = *reinterpret_cast<unsigned*>(&h0);
    o.y = *reinterpret_cast<unsigned*>(&h1);
    ((uint2*)d_xh)[i] = o;
}

__global__ void convw1_k(const float* __restrict__ W)
{
    int i = blockIdx.x * 256 + threadIdx.x;
    if (i >= F_IN * HC / 4) return;
    float4 v = ((const float4*)W)[i];
    __half2 h0 = __floats2half2_rn(v.x, v.y), h1 = __floats2half2_rn(v.z, v.w);
    uint2 o;
    o.x = *reinterpret_cast<unsigned*>(&h0);
    o.y = *reinterpret_cast<unsigned*>(&h1);
    ((uint2*)d_w1h)[i] = o;
}

__global__ void convw2_k(const float* __restrict__ W)
{
    int i = blockIdx.x * 256 + threadIdx.x;
    if (i >= HC * OUTD / 2) return;
    float2 v = ((const float2*)W)[i];
    unsigned h, l;
    split2h(v.x, v.y, h, l);
    ((unsigned*)d_w2h)[i] = h;
    ((unsigned*)d_w2l)[i] = l;
}

// ---------------- CSR build ----------------
__global__ void zero_deg_k()
{
    int i = blockIdx.x * blockDim.x + threadIdx.x;
    if (i < N_NODES) d_deg[i] = 0;
}

__global__ void hist_k(const int* __restrict__ ei)
{
    int e = blockIdx.x * blockDim.x + threadIdx.x;
    if (e >= N_EDGES) return;
    atomicAdd(&d_deg[ei[N_EDGES + e]], 1);
}

__global__ __launch_bounds__(1024) void scan_k()
{
    __shared__ int wsum[32];
    const int tid = threadIdx.x;
    const int ITEMS = (N_NODES + 1023) / 1024;   // 30
    int base = tid * ITEMS;
    int sum = 0;
#pragma unroll 4
    for (int i = 0; i < ITEMS; i++) {
        int idx = base + i;
        if (idx < N_NODES) sum += d_deg[idx];
    }
    int lane = tid & 31, wid = tid >> 5;
    int v = sum;
#pragma unroll
    for (int o = 1; o < 32; o <<= 1) {
        int y = __shfl_up_sync(0xFFFFFFFFu, v, o);
        if (lane >= o) v += y;
    }
    if (lane == 31) wsum[wid] = v;
    __syncthreads();
    if (wid == 0) {
        int w = wsum[lane];
#pragma unroll
        for (int o = 1; o < 32; o <<= 1) {
            int y = __shfl_up_sync(0xFFFFFFFFu, w, o);
            if (lane >= o) w += y;
        }
        wsum[lane] = w;
    }
    __syncthreads();
    int run = v - sum + (wid ? wsum[wid - 1] : 0);
#pragma unroll 4
    for (int i = 0; i < ITEMS; i++) {
        int idx = base + i;
        if (idx < N_NODES) {
            d_rowptr[idx] = run;
            d_cursor[idx] = run;
            run += d_deg[idx];
        }
    }
    if (tid == 1023) d_rowptr[N_NODES] = wsum[31];
}

__global__ void scatter_k(const int* __restrict__ ei)
{
    int e = blockIdx.x * blockDim.x + threadIdx.x;
    if (e >= N_EDGES) return;
    int s = ei[e], d = ei[N_EDGES + e];
    int p = atomicAdd(&d_cursor[d], 1);
    d_csr_src[p] = s;
}

// ---------------- GEMM1: fp16, K-tile 64, cp.async 2-stage, ldmatrix, 2 CTA/SM ----------------
// stage: [A: 128 rows x 72 halves = 18432 B][B: 64 rows x 136 halves = 17408 B]
#define G1_BH    18432
#define G1_STAGE 35840

__global__ __launch_bounds__(256, 2) void gemm1_mma(
    const __half* __restrict__ Ax, const __half* __restrict__ Bh16,
    const float* __restrict__ att_s, const float* __restrict__ att_d,
    __half* __restrict__ C, int M)
{
    extern __shared__ char dsm[];
    const unsigned sbase = smem_u32(dsm);
    const int tid = threadIdx.x, lane = tid & 31, wid = tid >> 5;
    const int g = lane >> 2, t = lane & 3;
    const int wm = wid >> 2, wn = wid & 3;     // 2x4 warps, warp tile 64x32
    const int by = blockIdx.y, bx = blockIdx.x;
    const int gRow0 = by * 128;
    float acc[4][4][4] = {};

    const unsigned aLane = (unsigned)((wm * 64 + (lane & 15)) * 144 + ((lane & 16) ? 16 : 0));
    const unsigned bLane = (unsigned)((lane & 15) * 272 + wn * 64 + ((lane & 16) ? 16 : 0));

    auto issue = [&](int kt, int st) {
        unsigned sb = sbase + st * G1_STAGE;
#pragma unroll
        for (int i = 0; i < 4; i++) {
            int ch = tid + 256 * i;
            int r = ch >> 3, c = ch & 7;
            long gr = gRow0 + r;
            CPA16(sb + r * 144 + c * 16, Ax + (size_t)gr * F_IN + kt * 64 + c * 8, (gr < M) ? 16 : 0);
        }
#pragma unroll
        for (int i = 0; i < 4; i++) {
            int ch = tid + 256 * i;
            int r = ch >> 4, c = ch & 15;
            CPA16(sb + G1_BH + r * 272 + c * 16, Bh16 + (size_t)(kt * 64 + r) * HC + bx * 128 + c * 8, 16);
        }
        asm volatile("cp.async.commit_group;\n" ::: "memory");
    };

    issue(0, 0);
    for (int kt = 0; kt < F_IN / 64; kt++) {
        if (kt < F_IN / 64 - 1) {
            issue(kt + 1, (kt + 1) & 1);
            asm volatile("cp.async.wait_group 1;\n" ::: "memory");
        } else {
            asm volatile("cp.async.wait_group 0;\n" ::: "memory");
        }
        __syncthreads();
        unsigned sb = sbase + (kt & 1) * G1_STAGE;
#pragma unroll
        for (int s = 0; s < 4; s++) {
            unsigned ah[4][4];
#pragma unroll
            for (int mt = 0; mt < 4; mt++)
                ldsm_x4(ah[mt][0], ah[mt][1], ah[mt][2], ah[mt][3],
                        sb + aLane + mt * 2304 + s * 32);
#pragma unroll
            for (int p = 0; p < 2; p++) {
                unsigned h0, h1, h2, h3;
                ldsm_x4_t(h0, h1, h2, h3, sb + G1_BH + bLane + s * 4352 + p * 32);
#pragma unroll
                for (int mt = 0; mt < 4; mt++) {
                    mma_f16(acc[mt][p * 2],     ah[mt], h0, h1);
                    mma_f16(acc[mt][p * 2 + 1], ah[mt], h2, h3);
                }
            }
        }
        __syncthreads();
    }
    // store C tile as fp16
#pragma unroll
    for (int mt = 0; mt < 4; mt++) {
        int r0 = gRow0 + wm * 64 + mt * 16 + g;
        int r1 = r0 + 8;
#pragma unroll
        for (int nt = 0; nt < 4; nt++) {
            int col = bx * 128 + wn * 32 + nt * 8 + 2 * t;
            if (r0 < M) *(__half2*)(C + (size_t)r0 * HC + col) = __floats2half2_rn(acc[mt][nt][0], acc[mt][nt][1]);
            if (r1 < M) *(__half2*)(C + (size_t)r1 * HC + col) = __floats2half2_rn(acc[mt][nt][2], acc[mt][nt][3]);
        }
    }
    // fused score epilogue
    float* sred = reinterpret_cast<float*>(dsm);   // [4][128][2]
    const float* as = att_s + bx * CDIM;
    const float* ad = att_d + bx * CDIM;
    float pss[4][2] = {}, psd[4][2] = {};
#pragma unroll
    for (int nt = 0; nt < 4; nt++) {
        int col = wn * 32 + nt * 8 + 2 * t;
        float a0 = as[col], a1 = as[col + 1];
        float e0 = ad[col], e1 = ad[col + 1];
#pragma unroll
        for (int mt = 0; mt < 4; mt++) {
            pss[mt][0] += acc[mt][nt][0] * a0 + acc[mt][nt][1] * a1;
            pss[mt][1] += acc[mt][nt][2] * a0 + acc[mt][nt][3] * a1;
            psd[mt][0] += acc[mt][nt][0] * e0 + acc[mt][nt][1] * e1;
            psd[mt][1] += acc[mt][nt][2] * e0 + acc[mt][nt][3] * e1;
        }
    }
#pragma unroll
    for (int o = 1; o <= 2; o <<= 1)
#pragma unroll
        for (int mt = 0; mt < 4; mt++)
#pragma unroll
            for (int rh = 0; rh < 2; rh++) {
                pss[mt][rh] += __shfl_xor_sync(0xFFFFFFFFu, pss[mt][rh], o);
                psd[mt][rh] += __shfl_xor_sync(0xFFFFFFFFu, psd[mt][rh], o);
            }
    if (t == 0) {
#pragma unroll
        for (int mt = 0; mt < 4; mt++)
#pragma unroll
            for (int rh = 0; rh < 2; rh++) {
                int rl = wm * 64 + mt * 16 + rh * 8 + g;
                sred[(wn * 128 + rl) * 2 + 0] = pss[mt][rh];
                sred[(wn * 128 + rl) * 2 + 1] = psd[mt][rh];
            }
    }
    __syncthreads();
    {
        int rl = tid >> 1, which = tid & 1;
        float sum = sred[(0 * 128 + rl) * 2 + which] + sred[(1 * 128 + rl) * 2 + which]
                  + sred[(2 * 128 + rl) * 2 + which] + sred[(3 * 128 + rl) * 2 + which];
        int row = gRow0 + rl;
        if (row < M) {
            if (which) d_adst1[row * HEADS + bx] = sum;
            else       d_asrc1[row * HEADS + bx] = sum;
        }
    }
}

// ---------------- layer-1 aggregation: per 4-head group, evict-last gathers ----------------
__global__ __launch_bounds__(128) void agg1_k(const float* __restrict__ b1, int h0)
{
    __shared__ int   s_src[32];
    __shared__ float s_w[4][32];
    const int n = blockIdx.x;
    const int hw = threadIdx.x >> 5, lane = threadIdx.x & 31;
    const int h = h0 + hw;
    const unsigned long long pol = mk_policy_el();
    const float adst = d_adst1[n * HEADS + h];
    const float ws = __expf(lrelu(d_asrc1[n * HEADS + h] + adst));
    const size_t rowoff = (size_t)h * CDIM + lane * 4;

    float4 acc = make_float4(0.f, 0.f, 0.f, 0.f);
    acc_h4_el(acc, d_h1h + (size_t)n * HC + rowoff, ws, pol);
    float denom = ws;

    const int beg = d_rowptr[n], end = d_rowptr[n + 1];
    for (int c0 = beg; c0 < end; c0 += 32) {
        const int m = min(32, end - c0);
        if (hw == 0 && lane < m) s_src[lane] = d_csr_src[c0 + lane];
        __syncthreads();
        if (lane < m)
            s_w[hw][lane] = __expf(lrelu(__ldg(&d_asrc1[s_src[lane] * HEADS + h]) + adst));
        __syncwarp();
        int jm = m & ~3;
        for (int j = 0; j < jm; j += 4) {
            int s0 = s_src[j], s1 = s_src[j + 1], s2 = s_src[j + 2], s3 = s_src[j + 3];
            float w0 = s_w[hw][j], w1 = s_w[hw][j + 1], w2 = s_w[hw][j + 2], w3 = s_w[hw][j + 3];
            uint2 r0 = ldg_el(d_h1h + (size_t)s0 * HC + rowoff, pol);
            uint2 r1 = ldg_el(d_h1h + (size_t)s1 * HC + rowoff, pol);
            uint2 r2 = ldg_el(d_h1h + (size_t)s2 * HC + rowoff, pol);
            uint2 r3 = ldg_el(d_h1h + (size_t)s3 * HC + rowoff, pol);
            float2 a0 = __half22float2(*reinterpret_cast<const __half2*>(&r0.x));
            float2 b0 = __half22float2(*reinterpret_cast<const __half2*>(&r0.y));
            float2 a1 = __half22float2(*reinterpret_cast<const __half2*>(&r1.x));
            float2 b1v = __half22float2(*reinterpret_cast<const __half2*>(&r1.y));
            float2 a2 = __half22float2(*reinterpret_cast<const __half2*>(&r2.x));
            float2 b2v = __half22float2(*reinterpret_cast<const __half2*>(&r2.y));
            float2 a3 = __half22float2(*reinterpret_cast<const __half2*>(&r3.x));
            float2 b3v = __half22float2(*reinterpret_cast<const __half2*>(&r3.y));
            acc.x += w0 * a0.x + w1 * a1.x + w2 * a2.x + w3 * a3.x;
            acc.y += w0 * a0.y + w1 * a1.y + w2 * a2.y + w3 * a3.y;
            acc.z += w0 * b0.x + w1 * b1v.x + w2 * b2v.x + w3 * b3v.x;
            acc.w += w0 * b0.y + w1 * b1v.y + w2 * b2v.y + w3 * b3v.y;
            denom += w0 + w1 + w2 + w3;
        }
        for (int j = jm; j < m; j++) {
            float w = s_w[hw][j];
            acc_h4_el(acc, d_h1h + (size_t)s_src[j] * HC + rowoff, w, pol);
            denom += w;
        }
        __syncthreads();
    }
    float inv = 1.f / (denom + 1e-16f);
    float4 bv = *(const float4*)(b1 + rowoff);
    float4 r;
    r.x = acc.x * inv + bv.x;
    r.y = acc.y * inv + bv.y;
    r.z = acc.z * inv + bv.z;
    r.w = acc.w * inv + bv.w;
    r.x = r.x > 0.f ? r.x : expm1f(r.x);
    r.y = r.y > 0.f ? r.y : expm1f(r.y);
    r.z = r.z > 0.f ? r.z : expm1f(r.z);
    r.w = r.w > 0.f ? r.w : expm1f(r.w);
    __half2 o0 = __floats2half2_rn(r.x, r.y);
    __half2 o1 = __floats2half2_rn(r.z, r.w);
    unsigned long long pack = (unsigned long long)*reinterpret_cast<unsigned*>(&o0)
                            | ((unsigned long long)*reinterpret_cast<unsigned*>(&o1) << 32);
    __stcs((unsigned long long*)(d_agg1h + (size_t)n * HC + rowoff), pack);
}

// ---------------- GEMM2: fp16 A, W2 fp16 hi+lo, cp.async 2-stage, ldmatrix, 2 CTA/SM ------------
// stage layout: [A: 128 x 40 halves = 10240 B][Bh: 32 x 72 halves = 4608 B][Bl: 4608 B]
#define G2_BHOF  10240
#define G2_BLOF  14848
#define G2_STAGE 19456

__global__ __launch_bounds__(256, 2) void gemm2_mma(
    const __half* __restrict__ A, const __half* __restrict__ Bh16, const __half* __restrict__ Bl16,
    const float* __restrict__ att_s, const float* __restrict__ att_d,
    float* __restrict__ C, int M)
{
    extern __shared__ char dsm[];
    const unsigned sbase = smem_u32(dsm);
    const int tid = threadIdx.x, lane = tid & 31, wid = tid >> 5;
    const int g = lane >> 2, t = lane & 3;
    const int wm = wid >> 2, wn = wid & 3;     // 2x4 warps, warp tile 64x16
    const int by = blockIdx.x;
    const int gRow0 = by * 128;
    float acc[4][2][4] = {};

    const int ar0 = tid >> 2, ar1 = (tid + 256) >> 2, acc4 = (tid & 3);
    const int br = tid >> 3, bcc = (tid & 7);

    const unsigned aLane = (unsigned)((wm * 64 + (lane & 15)) * 80 + ((lane & 16) ? 16 : 0));
    const unsigned bLane = (unsigned)((lane & 15) * 144 + wn * 32 + ((lane & 16) ? 16 : 0));

    auto issue = [&](int kt, int st) {
        unsigned sb = sbase + st * G2_STAGE;
        {
            long r = gRow0 + ar0;
            CPA16(sb + ar0 * 80 + acc4 * 16, A + (size_t)r * HC + kt * 32 + acc4 * 8, (r < M) ? 16 : 0);
            r = gRow0 + ar1;
            CPA16(sb + ar1 * 80 + acc4 * 16, A + (size_t)r * HC + kt * 32 + acc4 * 8, (r < M) ? 16 : 0);
        }
        CPA16(sb + G2_BHOF + br * 144 + bcc * 16, Bh16 + (size_t)(kt * 32 + br) * OUTD + bcc * 8, 16);
        CPA16(sb + G2_BLOF + br * 144 + bcc * 16, Bl16 + (size_t)(kt * 32 + br) * OUTD + bcc * 8, 16);
        asm volatile("cp.async.commit_group;\n" ::: "memory");
    };

    issue(0, 0);
    for (int kt = 0; kt < HC / 32; kt++) {
        if (kt < HC / 32 - 1) {
            issue(kt + 1, (kt + 1) & 1);
            asm volatile("cp.async.wait_group 1;\n" ::: "memory");
        } else {
            asm volatile("cp.async.wait_group 0;\n" ::: "memory");
        }
        __syncthreads();
        unsigned sb = sbase + (kt & 1) * G2_STAGE;
#pragma unroll
        for (int s = 0; s < 2; s++) {
            unsigned ah[4][4];
#pragma unroll
            for (int mt = 0; mt < 4; mt++)
                ldsm_x4(ah[mt][0], ah[mt][1], ah[mt][2], ah[mt][3],
                        sb + aLane + mt * 1280 + s * 32);
            unsigned h0, h1, h2, h3, l0, l1, l2, l3;
            ldsm_x4_t(h0, h1, h2, h3, sb + G2_BHOF + bLane + s * 2304);
            ldsm_x4_t(l0, l1, l2, l3, sb + G2_BLOF + bLane + s * 2304);
#pragma unroll
            for (int mt = 0; mt < 4; mt++) {
                mma_f16(acc[mt][0], ah[mt], h0, h1);
                mma_f16(acc[mt][0], ah[mt], l0, l1);
                mma_f16(acc[mt][1], ah[mt], h2, h3);
                mma_f16(acc[mt][1], ah[mt], l2, l3);
            }
        }
        __syncthreads();
    }
    // store C tile (fp32)
#pragma unroll
    for (int mt = 0; mt < 4; mt++) {
        int r0 = gRow0 + wm * 64 + mt * 16 + g;
        int r1 = r0 + 8;
#pragma unroll
        for (int nt = 0; nt < 2; nt++) {
            int col = wn * 16 + nt * 8 + 2 * t;
            if (r0 < M) *(float2*)(C + (size_t)r0 * OUTD + col) = make_float2(acc[mt][nt][0], acc[mt][nt][1]);
            if (r1 < M) *(float2*)(C + (size_t)r1 * OUTD + col) = make_float2(acc[mt][nt][2], acc[mt][nt][3]);
        }
    }
    // fused score epilogue
    float* sred = reinterpret_cast<float*>(dsm);   // [4][128][2]
    float pss[4][2] = {}, psd[4][2] = {};
#pragma unroll
    for (int nt = 0; nt < 2; nt++) {
        int col = wn * 16 + nt * 8 + 2 * t;
        float a0 = att_s[col], a1 = att_s[col + 1];
        float e0 = att_d[col], e1 = att_d[col + 1];
#pragma unroll
        for (int mt = 0; mt < 4; mt++) {
            pss[mt][0] += acc[mt][nt][0] * a0 + acc[mt][nt][1] * a1;
            pss[mt][1] += acc[mt][nt][2] * a0 + acc[mt][nt][3] * a1;
            psd[mt][0] += acc[mt][nt][0] * e0 + acc[mt][nt][1] * e1;
            psd[mt][1] += acc[mt][nt][2] * e0 + acc[mt][nt][3] * e1;
        }
    }
#pragma unroll
    for (int o = 1; o <= 2; o <<= 1)
#pragma unroll
        for (int mt = 0; mt < 4; mt++)
#pragma unroll
            for (int rh = 0; rh < 2; rh++) {
                pss[mt][rh] += __shfl_xor_sync(0xFFFFFFFFu, pss[mt][rh], o);
                psd[mt][rh] += __shfl_xor_sync(0xFFFFFFFFu, psd[mt][rh], o);
            }
    if (t == 0) {
#pragma unroll
        for (int mt = 0; mt < 4; mt++)
#pragma unroll
            for (int rh = 0; rh < 2; rh++) {
                int rl = wm * 64 + mt * 16 + rh * 8 + g;
                sred[(wn * 128 + rl) * 2 + 0] = pss[mt][rh];
                sred[(wn * 128 + rl) * 2 + 1] = psd[mt][rh];
            }
    }
    __syncthreads();
    {
        int rl = tid >> 1, which = tid & 1;
        float sum = sred[(0 * 128 + rl) * 2 + which] + sred[(1 * 128 + rl) * 2 + which]
                  + sred[(2 * 128 + rl) * 2 + which] + sred[(3 * 128 + rl) * 2 + which];
        int row = gRow0 + rl;
        if (row < M) {
            if (which) d_adst2[row] = sum;
            else       d_asrc2[row] = sum;
        }
    }
}

// ---------------- layer-2 one-pass aggregation + bias + log_softmax (MLP-4) ----------------
__global__ __launch_bounds__(256) void agg2_k(float* __restrict__ out, const float* __restrict__ b2)
{
    int n = blockIdx.x * 8 + (threadIdx.x >> 5);
    int lane = threadIdx.x & 31;
    if (n >= N_NODES) return;
    float adst = d_adst2[n];
    float ws = __expf(lrelu(d_asrc2[n] + adst));
    const float* hp = d_h2 + (size_t)n * OUTD;
    float acc0 = ws * hp[lane], acc1 = ws * hp[lane + 32];
    float denom = ws;
    const int beg = d_rowptr[n], end = d_rowptr[n + 1];
    int j = beg;
    for (; j + 4 <= end; j += 4) {
        int s0 = __ldg(&d_csr_src[j]);
        int s1 = __ldg(&d_csr_src[j + 1]);
        int s2 = __ldg(&d_csr_src[j + 2]);
        int s3 = __ldg(&d_csr_src[j + 3]);
        float w0 = __expf(lrelu(__ldg(&d_asrc2[s0]) + adst));
        float w1 = __expf(lrelu(__ldg(&d_asrc2[s1]) + adst));
        float w2 = __expf(lrelu(__ldg(&d_asrc2[s2]) + adst));
        float w3 = __expf(lrelu(__ldg(&d_asrc2[s3]) + adst));
        const float* p0 = d_h2 + (size_t)s0 * OUTD;
        const float* p1 = d_h2 + (size_t)s1 * OUTD;
        const float* p2 = d_h2 + (size_t)s2 * OUTD;
        const float* p3 = d_h2 + (size_t)s3 * OUTD;
        float f00 = p0[lane], f01 = p0[lane + 32];
        float f10 = p1[lane], f11 = p1[lane + 32];
        float f20 = p2[lane], f21 = p2[lane + 32];
        float f30 = p3[lane], f31 = p3[lane + 32];
        acc0 += w0 * f00 + w1 * f10 + w2 * f20 + w3 * f30;
        acc1 += w0 * f01 + w1 * f11 + w2 * f21 + w3 * f31;
        denom += w0 + w1 + w2 + w3;
    }
    for (; j < end; j++) {
        int s = __ldg(&d_csr_src[j]);
        float w = __expf(lrelu(__ldg(&d_asrc2[s]) + adst));
        const float* sp = d_h2 + (size_t)s * OUTD;
        acc0 += w * sp[lane];
        acc1 += w * sp[lane + 32];
        denom += w;
    }
    float inv = 1.f / (denom + 1e-16f);
    float x0 = acc0 * inv + b2[lane];
    float x1 = acc1 * inv + b2[lane + 32];
    float mx = fmaxf(x0, x1);
#pragma unroll
    for (int o = 16; o; o >>= 1) mx = fmaxf(mx, __shfl_xor_sync(0xFFFFFFFFu, mx, o));
    float sm = __expf(x0 - mx) + __expf(x1 - mx);
#pragma unroll
    for (int o = 16; o; o >>= 1) sm += __shfl_xor_sync(0xFFFFFFFFu, sm, o);
    float lse = mx + logf(sm);
    out[(size_t)n * OUTD + lane] = x0 - lse;
    out[(size_t)n * OUTD + lane + 32] = x1 - lse;
}

// ---------------- launch ----------------
extern "C" void kernel_launch(void* const* d_in, const int* in_sizes, int n_in,
                              void* d_out, int out_size)
{
    const float* x   = (const float*)d_in[0];
    const int*   ei  = (const int*)  d_in[1];
    const float* W1  = (const float*)d_in[2];
    const float* as1 = (const float*)d_in[3];
    const float* ad1 = (const float*)d_in[4];
    const float* b1  = (const float*)d_in[5];
    const float* W2  = (const float*)d_in[6];
    const float* as2 = (const float*)d_in[7];
    const float* ad2 = (const float*)d_in[8];
    const float* b2  = (const float*)d_in[9];
    float* out = (float*)d_out;

    __half *h1p, *agg1hp, *xhp, *w1hp, *w2hp, *w2lp;
    float *h2p;
    cudaGetSymbolAddress((void**)&h1p,    d_h1h);
    cudaGetSymbolAddress((void**)&agg1hp, d_agg1h);
    cudaGetSymbolAddress((void**)&xhp,    d_xh);
    cudaGetSymbolAddress((void**)&w1hp,   d_w1h);
    cudaGetSymbolAddress((void**)&w2hp,   d_w2h);
    cudaGetSymbolAddress((void**)&w2lp,   d_w2l);
    cudaGetSymbolAddress((void**)&h2p,    d_h2);

    cudaFuncSetAttribute(gemm1_mma, cudaFuncAttributeMaxDynamicSharedMemorySize, 2 * G1_STAGE);
    cudaFuncSetAttribute(gemm2_mma, cudaFuncAttributeMaxDynamicSharedMemorySize, 2 * G2_STAGE);

    // launch order keeps gemm1 in the profiled slot (#4)
    zero_deg_k<<<(N_NODES + 255) / 256, 256>>>();
    convx_k<<<(N_NODES * F_IN / 4 + 255) / 256, 256>>>(x);
    convw1_k<<<(F_IN * HC / 4 + 255) / 256, 256>>>(W1);
    {
        dim3 g(HC / 128, (N_NODES + 127) / 128);
        gemm1_mma<<<g, 256, 2 * G1_STAGE>>>(xhp, w1hp, as1, ad1, h1p, N_NODES);
    }
    convw2_k<<<(HC * OUTD / 2 + 255) / 256, 256>>>(W2);
    hist_k<<<(N_EDGES + 255) / 256, 256>>>(ei);
    scan_k<<<1, 1024>>>();
    scatter_k<<<(N_EDGES + 255) / 256, 256>>>(ei);

    // layer-1 aggregation: two serialized head-group passes (30.7 MB L2-resident each)
    agg1_k<<<N_NODES, 128>>>(b1, 0);
    agg1_k<<<N_NODES, 128>>>(b1, 4);

    // layer 2
    gemm2_mma<<<(N_NODES + 127) / 128, 256, 2 * G2_STAGE>>>(agg1hp, w2hp, w2lp, as2, ad2, h2p, N_NODES);
    agg2_k<<<(N_NODES + 7) / 8, 256>>>(out, b2);
}

// round 17
// speedup vs baseline: 1.0212x; 1.0212x over previous
#include <cuda_runtime.h>
#include <cuda_bf16.h>
#include <cuda_fp16.h>
#include <math.h>

#define N_NODES 30000
#define F_IN    256
#define N_EDGES 300000
#define HEADS   8
#define CDIM    128
#define HC      1024
#define OUTD    64
#define NEG_SLOPE 0.2f

// ---------------- scratch ----------------
__device__ __align__(256) __half d_h1h  [(size_t)N_NODES * HC];  // 61.4 MB
__device__ __align__(256) __half d_agg1h[(size_t)N_NODES * HC];  // 61.4 MB
__device__ __align__(256) __half d_xh   [(size_t)N_NODES * F_IN]; // 15.4 MB
__device__ __align__(256) __half d_w1h  [F_IN * HC];              // W1 fp16
__device__ __align__(256) __half d_w2h  [HC * OUTD];              // W2 hi fp16
__device__ __align__(256) __half d_w2l  [HC * OUTD];              // W2 lo fp16
__device__ __align__(256) float  d_asrc1[N_NODES * HEADS];
__device__ __align__(256) float  d_adst1[N_NODES * HEADS];
__device__ __align__(256) float  d_h2  [(size_t)N_NODES * OUTD];
__device__ __align__(256) float  d_asrc2[N_NODES];
__device__ __align__(256) float  d_adst2[N_NODES];
__device__ __align__(256) int    d_deg   [N_NODES];
__device__ __align__(256) int    d_rowptr[N_NODES + 1];
__device__ __align__(256) int    d_cursor[N_NODES];
__device__ __align__(256) int    d_csr_src[N_EDGES];

// ---------------- helpers ----------------
__device__ __forceinline__ float lrelu(float x) { return x > 0.f ? x : NEG_SLOPE * x; }

__device__ __forceinline__ unsigned smem_u32(const void* p) {
    unsigned a;
    asm("{ .reg .u64 t; cvta.to.shared.u64 t, %1; cvt.u32.u64 %0, t; }" : "=r"(a) : "l"(p));
    return a;
}

__device__ __forceinline__ void split2h(float x, float y, unsigned& h, unsigned& l) {
    __half hx = __float2half_rn(x);
    __half hy = __float2half_rn(y);
    float rx = x - __half2float(hx);
    float ry = y - __half2float(hy);
    __half lx = __float2half_rn(rx);
    __half ly = __float2half_rn(ry);
    h = (unsigned)__half_as_ushort(hx) | ((unsigned)__half_as_ushort(hy) << 16);
    l = (unsigned)__half_as_ushort(lx) | ((unsigned)__half_as_ushort(ly) << 16);
}

__device__ __forceinline__ void mma_f16(float* c, const unsigned* a, unsigned b0, unsigned b1) {
    asm volatile("mma.sync.aligned.m16n8k16.row.col.f32.f16.f16.f32 "
                 "{%0,%1,%2,%3}, {%4,%5,%6,%7}, {%8,%9}, {%0,%1,%2,%3};\n"
                 : "+f"(c[0]), "+f"(c[1]), "+f"(c[2]), "+f"(c[3])
                 : "r"(a[0]), "r"(a[1]), "r"(a[2]), "r"(a[3]), "r"(b0), "r"(b1));
}

__device__ __forceinline__ void ldsm_x4(unsigned& r0, unsigned& r1, unsigned& r2, unsigned& r3, unsigned a) {
    asm volatile("ldmatrix.sync.aligned.m8n8.x4.shared.b16 {%0,%1,%2,%3}, [%4];"
                 : "=r"(r0), "=r"(r1), "=r"(r2), "=r"(r3) : "r"(a));
}
__device__ __forceinline__ void ldsm_x4_t(unsigned& r0, unsigned& r1, unsigned& r2, unsigned& r3, unsigned a) {
    asm volatile("ldmatrix.sync.aligned.m8n8.x4.trans.shared.b16 {%0,%1,%2,%3}, [%4];"
                 : "=r"(r0), "=r"(r1), "=r"(r2), "=r"(r3) : "r"(a));
}

#define CPA16(dst, src, sz) \
    asm volatile("cp.async.cg.shared.global [%0], [%1], 16, %2;\n" :: "r"(dst), "l"(src), "r"(sz))

__device__ __forceinline__ void acc_h4(float4& acc, const __half* base, float w) {
    uint2 raw = __ldg((const uint2*)base);
    float2 u0 = __half22float2(*reinterpret_cast<const __half2*>(&raw.x));
    float2 u1 = __half22float2(*reinterpret_cast<const __half2*>(&raw.y));
    acc.x += w * u0.x; acc.y += w * u0.y; acc.z += w * u1.x; acc.w += w * u1.y;
}

// ---------------- conversion kernels ----------------
__global__ void convx_k(const float* __restrict__ x)
{
    int i = blockIdx.x * 256 + threadIdx.x;
    if (i >= N_NODES * F_IN / 4) return;
    float4 v = ((const float4*)x)[i];
    __half2 h0 = __floats2half2_rn(v.x, v.y), h1 = __floats2half2_rn(v.z, v.w);
    uint2 o;
    o.x = *reinterpret_cast<unsigned*>(&h0);
    o.y = *reinterpret_cast<unsigned*>(&h1);
    ((uint2*)d_xh)[i] = o;
}

__global__ void convw1_k(const float* __restrict__ W)
{
    int i = blockIdx.x * 256 + threadIdx.x;
    if (i >= F_IN * HC / 4) return;
    float4 v = ((const float4*)W)[i];
    __half2 h0 = __floats2half2_rn(v.x, v.y), h1 = __floats2half2_rn(v.z, v.w);
    uint2 o;
    o.x = *reinterpret_cast<unsigned*>(&h0);
    o.y = *reinterpret_cast<unsigned*>(&h1);
    ((uint2*)d_w1h)[i] = o;
}

__global__ void convw2_k(const float* __restrict__ W)
{
    int i = blockIdx.x * 256 + threadIdx.x;
    if (i >= HC * OUTD / 2) return;
    float2 v = ((const float2*)W)[i];
    unsigned h, l;
    split2h(v.x, v.y, h, l);
    ((unsigned*)d_w2h)[i] = h;
    ((unsigned*)d_w2l)[i] = l;
}

// ---------------- CSR build ----------------
__global__ void zero_deg_k()
{
    int i = blockIdx.x * blockDim.x + threadIdx.x;
    if (i < N_NODES) d_deg[i] = 0;
}

__global__ void hist_k(const int* __restrict__ ei)
{
    int e = blockIdx.x * blockDim.x + threadIdx.x;
    if (e >= N_EDGES) return;
    atomicAdd(&d_deg[ei[N_EDGES + e]], 1);
}

__global__ __launch_bounds__(1024) void scan_k()
{
    __shared__ int wsum[32];
    const int tid = threadIdx.x;
    const int ITEMS = (N_NODES + 1023) / 1024;   // 30
    int base = tid * ITEMS;
    int sum = 0;
#pragma unroll 4
    for (int i = 0; i < ITEMS; i++) {
        int idx = base + i;
        if (idx < N_NODES) sum += d_deg[idx];
    }
    int lane = tid & 31, wid = tid >> 5;
    int v = sum;
#pragma unroll
    for (int o = 1; o < 32; o <<= 1) {
        int y = __shfl_up_sync(0xFFFFFFFFu, v, o);
        if (lane >= o) v += y;
    }
    if (lane == 31) wsum[wid] = v;
    __syncthreads();
    if (wid == 0) {
        int w = wsum[lane];
#pragma unroll
        for (int o = 1; o < 32; o <<= 1) {
            int y = __shfl_up_sync(0xFFFFFFFFu, w, o);
            if (lane >= o) w += y;
        }
        wsum[lane] = w;
    }
    __syncthreads();
    int run = v - sum + (wid ? wsum[wid - 1] : 0);
#pragma unroll 4
    for (int i = 0; i < ITEMS; i++) {
        int idx = base + i;
        if (idx < N_NODES) {
            d_rowptr[idx] = run;
            d_cursor[idx] = run;
            run += d_deg[idx];
        }
    }
    if (tid == 1023) d_rowptr[N_NODES] = wsum[31];
}

__global__ void scatter_k(const int* __restrict__ ei)
{
    int e = blockIdx.x * blockDim.x + threadIdx.x;
    if (e >= N_EDGES) return;
    int s = ei[e], d = ei[N_EDGES + e];
    int p = atomicAdd(&d_cursor[d], 1);
    d_csr_src[p] = s;
}

// ---------------- GEMM1: fp16, K-tile 64, cp.async 2-stage, ldmatrix, 2 CTA/SM ----------------
// stage: [A: 128 rows x 72 halves = 18432 B][B: 64 rows x 136 halves = 17408 B]
#define G1_BH    18432
#define G1_STAGE 35840

__global__ __launch_bounds__(256, 2) void gemm1_mma(
    const __half* __restrict__ Ax, const __half* __restrict__ Bh16,
    const float* __restrict__ att_s, const float* __restrict__ att_d,
    __half* __restrict__ C, int M)
{
    extern __shared__ char dsm[];
    const unsigned sbase = smem_u32(dsm);
    const int tid = threadIdx.x, lane = tid & 31, wid = tid >> 5;
    const int g = lane >> 2, t = lane & 3;
    const int wm = wid >> 2, wn = wid & 3;     // 2x4 warps, warp tile 64x32
    const int by = blockIdx.y, bx = blockIdx.x;
    const int gRow0 = by * 128;
    float acc[4][4][4] = {};

    const unsigned aLane = (unsigned)((wm * 64 + (lane & 15)) * 144 + ((lane & 16) ? 16 : 0));
    const unsigned bLane = (unsigned)((lane & 15) * 272 + wn * 64 + ((lane & 16) ? 16 : 0));

    auto issue = [&](int kt, int st) {
        unsigned sb = sbase + st * G1_STAGE;
#pragma unroll
        for (int i = 0; i < 4; i++) {
            int ch = tid + 256 * i;
            int r = ch >> 3, c = ch & 7;
            long gr = gRow0 + r;
            CPA16(sb + r * 144 + c * 16, Ax + (size_t)gr * F_IN + kt * 64 + c * 8, (gr < M) ? 16 : 0);
        }
#pragma unroll
        for (int i = 0; i < 4; i++) {
            int ch = tid + 256 * i;
            int r = ch >> 4, c = ch & 15;
            CPA16(sb + G1_BH + r * 272 + c * 16, Bh16 + (size_t)(kt * 64 + r) * HC + bx * 128 + c * 8, 16);
        }
        asm volatile("cp.async.commit_group;\n" ::: "memory");
    };

    issue(0, 0);
    for (int kt = 0; kt < F_IN / 64; kt++) {
        if (kt < F_IN / 64 - 1) {
            issue(kt + 1, (kt + 1) & 1);
            asm volatile("cp.async.wait_group 1;\n" ::: "memory");
        } else {
            asm volatile("cp.async.wait_group 0;\n" ::: "memory");
        }
        __syncthreads();
        unsigned sb = sbase + (kt & 1) * G1_STAGE;
#pragma unroll
        for (int s = 0; s < 4; s++) {
            unsigned ah[4][4];
#pragma unroll
            for (int mt = 0; mt < 4; mt++)
                ldsm_x4(ah[mt][0], ah[mt][1], ah[mt][2], ah[mt][3],
                        sb + aLane + mt * 2304 + s * 32);
#pragma unroll
            for (int p = 0; p < 2; p++) {
                unsigned h0, h1, h2, h3;
                ldsm_x4_t(h0, h1, h2, h3, sb + G1_BH + bLane + s * 4352 + p * 32);
#pragma unroll
                for (int mt = 0; mt < 4; mt++) {
                    mma_f16(acc[mt][p * 2],     ah[mt], h0, h1);
                    mma_f16(acc[mt][p * 2 + 1], ah[mt], h2, h3);
                }
            }
        }
        __syncthreads();
    }
    // store C tile as fp16
#pragma unroll
    for (int mt = 0; mt < 4; mt++) {
        int r0 = gRow0 + wm * 64 + mt * 16 + g;
        int r1 = r0 + 8;
#pragma unroll
        for (int nt = 0; nt < 4; nt++) {
            int col = bx * 128 + wn * 32 + nt * 8 + 2 * t;
            if (r0 < M) *(__half2*)(C + (size_t)r0 * HC + col) = __floats2half2_rn(acc[mt][nt][0], acc[mt][nt][1]);
            if (r1 < M) *(__half2*)(C + (size_t)r1 * HC + col) = __floats2half2_rn(acc[mt][nt][2], acc[mt][nt][3]);
        }
    }
    // fused score epilogue
    float* sred = reinterpret_cast<float*>(dsm);   // [4][128][2]
    const float* as = att_s + bx * CDIM;
    const float* ad = att_d + bx * CDIM;
    float pss[4][2] = {}, psd[4][2] = {};
#pragma unroll
    for (int nt = 0; nt < 4; nt++) {
        int col = wn * 32 + nt * 8 + 2 * t;
        float a0 = as[col], a1 = as[col + 1];
        float e0 = ad[col], e1 = ad[col + 1];
#pragma unroll
        for (int mt = 0; mt < 4; mt++) {
            pss[mt][0] += acc[mt][nt][0] * a0 + acc[mt][nt][1] * a1;
            pss[mt][1] += acc[mt][nt][2] * a0 + acc[mt][nt][3] * a1;
            psd[mt][0] += acc[mt][nt][0] * e0 + acc[mt][nt][1] * e1;
            psd[mt][1] += acc[mt][nt][2] * e0 + acc[mt][nt][3] * e1;
        }
    }
#pragma unroll
    for (int o = 1; o <= 2; o <<= 1)
#pragma unroll
        for (int mt = 0; mt < 4; mt++)
#pragma unroll
            for (int rh = 0; rh < 2; rh++) {
                pss[mt][rh] += __shfl_xor_sync(0xFFFFFFFFu, pss[mt][rh], o);
                psd[mt][rh] += __shfl_xor_sync(0xFFFFFFFFu, psd[mt][rh], o);
            }
    if (t == 0) {
#pragma unroll
        for (int mt = 0; mt < 4; mt++)
#pragma unroll
            for (int rh = 0; rh < 2; rh++) {
                int rl = wm * 64 + mt * 16 + rh * 8 + g;
                sred[(wn * 128 + rl) * 2 + 0] = pss[mt][rh];
                sred[(wn * 128 + rl) * 2 + 1] = psd[mt][rh];
            }
    }
    __syncthreads();
    {
        int rl = tid >> 1, which = tid & 1;
        float sum = sred[(0 * 128 + rl) * 2 + which] + sred[(1 * 128 + rl) * 2 + which]
                  + sred[(2 * 128 + rl) * 2 + which] + sred[(3 * 128 + rl) * 2 + which];
        int row = gRow0 + rl;
        if (row < M) {
            if (which) d_adst1[row * HEADS + bx] = sum;
            else       d_asrc1[row * HEADS + bx] = sum;
        }
    }
}

// ---------------- layer-1 aggregation: ONE pass, 8 warps = all heads, fused bias+ELU ----------------
__global__ __launch_bounds__(256) void agg1_k(const float* __restrict__ b1)
{
    __shared__ int   s_src[32];
    __shared__ float s_w[HEADS][32];
    const int n = blockIdx.x;
    const int h = threadIdx.x >> 5, lane = threadIdx.x & 31;
    const float adst = d_adst1[n * HEADS + h];
    const float ws = __expf(lrelu(d_asrc1[n * HEADS + h] + adst));
    const size_t rowoff = (size_t)h * CDIM + lane * 4;

    float4 acc = make_float4(0.f, 0.f, 0.f, 0.f);
    acc_h4(acc, d_h1h + (size_t)n * HC + rowoff, ws);
    float denom = ws;

    const int beg = d_rowptr[n], end = d_rowptr[n + 1];
    for (int c0 = beg; c0 < end; c0 += 32) {
        const int m = min(32, end - c0);
        if (h == 0 && lane < m) s_src[lane] = d_csr_src[c0 + lane];
        __syncthreads();
        if (lane < m)
            s_w[h][lane] = __expf(lrelu(__ldg(&d_asrc1[s_src[lane] * HEADS + h]) + adst));
        __syncwarp();
        int jm = m & ~3;
        for (int j = 0; j < jm; j += 4) {
            int s0 = s_src[j], s1 = s_src[j + 1], s2 = s_src[j + 2], s3 = s_src[j + 3];
            float w0 = s_w[h][j], w1 = s_w[h][j + 1], w2 = s_w[h][j + 2], w3 = s_w[h][j + 3];
            uint2 r0 = __ldg((const uint2*)(d_h1h + (size_t)s0 * HC + rowoff));
            uint2 r1 = __ldg((const uint2*)(d_h1h + (size_t)s1 * HC + rowoff));
            uint2 r2 = __ldg((const uint2*)(d_h1h + (size_t)s2 * HC + rowoff));
            uint2 r3 = __ldg((const uint2*)(d_h1h + (size_t)s3 * HC + rowoff));
            float2 a0 = __half22float2(*reinterpret_cast<const __half2*>(&r0.x));
            float2 b0 = __half22float2(*reinterpret_cast<const __half2*>(&r0.y));
            float2 a1 = __half22float2(*reinterpret_cast<const __half2*>(&r1.x));
            float2 b1v = __half22float2(*reinterpret_cast<const __half2*>(&r1.y));
            float2 a2 = __half22float2(*reinterpret_cast<const __half2*>(&r2.x));
            float2 b2v = __half22float2(*reinterpret_cast<const __half2*>(&r2.y));
            float2 a3 = __half22float2(*reinterpret_cast<const __half2*>(&r3.x));
            float2 b3v = __half22float2(*reinterpret_cast<const __half2*>(&r3.y));
            acc.x += w0 * a0.x + w1 * a1.x + w2 * a2.x + w3 * a3.x;
            acc.y += w0 * a0.y + w1 * a1.y + w2 * a2.y + w3 * a3.y;
            acc.z += w0 * b0.x + w1 * b1v.x + w2 * b2v.x + w3 * b3v.x;
            acc.w += w0 * b0.y + w1 * b1v.y + w2 * b2v.y + w3 * b3v.y;
            denom += w0 + w1 + w2 + w3;
        }
        for (int j = jm; j < m; j++) {
            float w = s_w[h][j];
            acc_h4(acc, d_h1h + (size_t)s_src[j] * HC + rowoff, w);
            denom += w;
        }
        __syncthreads();
    }
    float inv = 1.f / (denom + 1e-16f);
    float4 bv = *(const float4*)(b1 + rowoff);
    float4 r;
    r.x = acc.x * inv + bv.x;
    r.y = acc.y * inv + bv.y;
    r.z = acc.z * inv + bv.z;
    r.w = acc.w * inv + bv.w;
    r.x = r.x > 0.f ? r.x : expm1f(r.x);
    r.y = r.y > 0.f ? r.y : expm1f(r.y);
    r.z = r.z > 0.f ? r.z : expm1f(r.z);
    r.w = r.w > 0.f ? r.w : expm1f(r.w);
    __half2 o0 = __floats2half2_rn(r.x, r.y);
    __half2 o1 = __floats2half2_rn(r.z, r.w);
    unsigned long long pack = (unsigned long long)*reinterpret_cast<unsigned*>(&o0)
                            | ((unsigned long long)*reinterpret_cast<unsigned*>(&o1) << 32);
    __stcs((unsigned long long*)(d_agg1h + (size_t)n * HC + rowoff), pack);
}

// ---------------- GEMM2: fp16 A, W2 fp16 hi+lo, cp.async 2-stage, ldmatrix, 2 CTA/SM ------------
// stage layout: [A: 128 x 40 halves = 10240 B][Bh: 32 x 72 halves = 4608 B][Bl: 4608 B]
#define G2_BHOF  10240
#define G2_BLOF  14848
#define G2_STAGE 19456

__global__ __launch_bounds__(256, 2) void gemm2_mma(
    const __half* __restrict__ A, const __half* __restrict__ Bh16, const __half* __restrict__ Bl16,
    const float* __restrict__ att_s, const float* __restrict__ att_d,
    float* __restrict__ C, int M)
{
    extern __shared__ char dsm[];
    const unsigned sbase = smem_u32(dsm);
    const int tid = threadIdx.x, lane = tid & 31, wid = tid >> 5;
    const int g = lane >> 2, t = lane & 3;
    const int wm = wid >> 2, wn = wid & 3;     // 2x4 warps, warp tile 64x16
    const int by = blockIdx.x;
    const int gRow0 = by * 128;
    float acc[4][2][4] = {};

    const int ar0 = tid >> 2, ar1 = (tid + 256) >> 2, acc4 = (tid & 3);
    const int br = tid >> 3, bcc = (tid & 7);

    const unsigned aLane = (unsigned)((wm * 64 + (lane & 15)) * 80 + ((lane & 16) ? 16 : 0));
    const unsigned bLane = (unsigned)((lane & 15) * 144 + wn * 32 + ((lane & 16) ? 16 : 0));

    auto issue = [&](int kt, int st) {
        unsigned sb = sbase + st * G2_STAGE;
        {
            long r = gRow0 + ar0;
            CPA16(sb + ar0 * 80 + acc4 * 16, A + (size_t)r * HC + kt * 32 + acc4 * 8, (r < M) ? 16 : 0);
            r = gRow0 + ar1;
            CPA16(sb + ar1 * 80 + acc4 * 16, A + (size_t)r * HC + kt * 32 + acc4 * 8, (r < M) ? 16 : 0);
        }
        CPA16(sb + G2_BHOF + br * 144 + bcc * 16, Bh16 + (size_t)(kt * 32 + br) * OUTD + bcc * 8, 16);
        CPA16(sb + G2_BLOF + br * 144 + bcc * 16, Bl16 + (size_t)(kt * 32 + br) * OUTD + bcc * 8, 16);
        asm volatile("cp.async.commit_group;\n" ::: "memory");
    };

    issue(0, 0);
    for (int kt = 0; kt < HC / 32; kt++) {
        if (kt < HC / 32 - 1) {
            issue(kt + 1, (kt + 1) & 1);
            asm volatile("cp.async.wait_group 1;\n" ::: "memory");
        } else {
            asm volatile("cp.async.wait_group 0;\n" ::: "memory");
        }
        __syncthreads();
        unsigned sb = sbase + (kt & 1) * G2_STAGE;
#pragma unroll
        for (int s = 0; s < 2; s++) {
            unsigned ah[4][4];
#pragma unroll
            for (int mt = 0; mt < 4; mt++)
                ldsm_x4(ah[mt][0], ah[mt][1], ah[mt][2], ah[mt][3],
                        sb + aLane + mt * 1280 + s * 32);
            unsigned h0, h1, h2, h3, l0, l1, l2, l3;
            ldsm_x4_t(h0, h1, h2, h3, sb + G2_BHOF + bLane + s * 2304);
            ldsm_x4_t(l0, l1, l2, l3, sb + G2_BLOF + bLane + s * 2304);
#pragma unroll
            for (int mt = 0; mt < 4; mt++) {
                mma_f16(acc[mt][0], ah[mt], h0, h1);
                mma_f16(acc[mt][0], ah[mt], l0, l1);
                mma_f16(acc[mt][1], ah[mt], h2, h3);
                mma_f16(acc[mt][1], ah[mt], l2, l3);
            }
        }
        __syncthreads();
    }
    // store C tile (fp32)
#pragma unroll
    for (int mt = 0; mt < 4; mt++) {
        int r0 = gRow0 + wm * 64 + mt * 16 + g;
        int r1 = r0 + 8;
#pragma unroll
        for (int nt = 0; nt < 2; nt++) {
            int col = wn * 16 + nt * 8 + 2 * t;
            if (r0 < M) *(float2*)(C + (size_t)r0 * OUTD + col) = make_float2(acc[mt][nt][0], acc[mt][nt][1]);
            if (r1 < M) *(float2*)(C + (size_t)r1 * OUTD + col) = make_float2(acc[mt][nt][2], acc[mt][nt][3]);
        }
    }
    // fused score epilogue
    float* sred = reinterpret_cast<float*>(dsm);   // [4][128][2]
    float pss[4][2] = {}, psd[4][2] = {};
#pragma unroll
    for (int nt = 0; nt < 2; nt++) {
        int col = wn * 16 + nt * 8 + 2 * t;
        float a0 = att_s[col], a1 = att_s[col + 1];
        float e0 = att_d[col], e1 = att_d[col + 1];
#pragma unroll
        for (int mt = 0; mt < 4; mt++) {
            pss[mt][0] += acc[mt][nt][0] * a0 + acc[mt][nt][1] * a1;
            pss[mt][1] += acc[mt][nt][2] * a0 + acc[mt][nt][3] * a1;
            psd[mt][0] += acc[mt][nt][0] * e0 + acc[mt][nt][1] * e1;
            psd[mt][1] += acc[mt][nt][2] * e0 + acc[mt][nt][3] * e1;
        }
    }
#pragma unroll
    for (int o = 1; o <= 2; o <<= 1)
#pragma unroll
        for (int mt = 0; mt < 4; mt++)
#pragma unroll
            for (int rh = 0; rh < 2; rh++) {
                pss[mt][rh] += __shfl_xor_sync(0xFFFFFFFFu, pss[mt][rh], o);
                psd[mt][rh] += __shfl_xor_sync(0xFFFFFFFFu, psd[mt][rh], o);
            }
    if (t == 0) {
#pragma unroll
        for (int mt = 0; mt < 4; mt++)
#pragma unroll
            for (int rh = 0; rh < 2; rh++) {
                int rl = wm * 64 + mt * 16 + rh * 8 + g;
                sred[(wn * 128 + rl) * 2 + 0] = pss[mt][rh];
                sred[(wn * 128 + rl) * 2 + 1] = psd[mt][rh];
            }
    }
    __syncthreads();
    {
        int rl = tid >> 1, which = tid & 1;
        float sum = sred[(0 * 128 + rl) * 2 + which] + sred[(1 * 128 + rl) * 2 + which]
                  + sred[(2 * 128 + rl) * 2 + which] + sred[(3 * 128 + rl) * 2 + which];
        int row = gRow0 + rl;
        if (row < M) {
            if (which) d_adst2[row] = sum;
            else       d_asrc2[row] = sum;
        }
    }
}

// ---------------- layer-2 one-pass aggregation + bias + log_softmax (MLP-4) ----------------
__global__ __launch_bounds__(256) void agg2_k(float* __restrict__ out, const float* __restrict__ b2)
{
    int n = blockIdx.x * 8 + (threadIdx.x >> 5);
    int lane = threadIdx.x & 31;
    if (n >= N_NODES) return;
    float adst = d_adst2[n];
    float ws = __expf(lrelu(d_asrc2[n] + adst));
    const float* hp = d_h2 + (size_t)n * OUTD;
    float acc0 = ws * hp[lane], acc1 = ws * hp[lane + 32];
    float denom = ws;
    const int beg = d_rowptr[n], end = d_rowptr[n + 1];
    int j = beg;
    for (; j + 4 <= end; j += 4) {
        int s0 = __ldg(&d_csr_src[j]);
        int s1 = __ldg(&d_csr_src[j + 1]);
        int s2 = __ldg(&d_csr_src[j + 2]);
        int s3 = __ldg(&d_csr_src[j + 3]);
        float w0 = __expf(lrelu(__ldg(&d_asrc2[s0]) + adst));
        float w1 = __expf(lrelu(__ldg(&d_asrc2[s1]) + adst));
        float w2 = __expf(lrelu(__ldg(&d_asrc2[s2]) + adst));
        float w3 = __expf(lrelu(__ldg(&d_asrc2[s3]) + adst));
        const float* p0 = d_h2 + (size_t)s0 * OUTD;
        const float* p1 = d_h2 + (size_t)s1 * OUTD;
        const float* p2 = d_h2 + (size_t)s2 * OUTD;
        const float* p3 = d_h2 + (size_t)s3 * OUTD;
        float f00 = p0[lane], f01 = p0[lane + 32];
        float f10 = p1[lane], f11 = p1[lane + 32];
        float f20 = p2[lane], f21 = p2[lane + 32];
        float f30 = p3[lane], f31 = p3[lane + 32];
        acc0 += w0 * f00 + w1 * f10 + w2 * f20 + w3 * f30;
        acc1 += w0 * f01 + w1 * f11 + w2 * f21 + w3 * f31;
        denom += w0 + w1 + w2 + w3;
    }
    for (; j < end; j++) {
        int s = __ldg(&d_csr_src[j]);
        float w = __expf(lrelu(__ldg(&d_asrc2[s]) + adst));
        const float* sp = d_h2 + (size_t)s * OUTD;
        acc0 += w * sp[lane];
        acc1 += w * sp[lane + 32];
        denom += w;
    }
    float inv = 1.f / (denom + 1e-16f);
    float x0 = acc0 * inv + b2[lane];
    float x1 = acc1 * inv + b2[lane + 32];
    float mx = fmaxf(x0, x1);
#pragma unroll
    for (int o = 16; o; o >>= 1) mx = fmaxf(mx, __shfl_xor_sync(0xFFFFFFFFu, mx, o));
    float sm = __expf(x0 - mx) + __expf(x1 - mx);
#pragma unroll
    for (int o = 16; o; o >>= 1) sm += __shfl_xor_sync(0xFFFFFFFFu, sm, o);
    float lse = mx + logf(sm);
    out[(size_t)n * OUTD + lane] = x0 - lse;
    out[(size_t)n * OUTD + lane + 32] = x1 - lse;
}

// ---------------- launch ----------------
extern "C" void kernel_launch(void* const* d_in, const int* in_sizes, int n_in,
                              void* d_out, int out_size)
{
    const float* x   = (const float*)d_in[0];
    const int*   ei  = (const int*)  d_in[1];
    const float* W1  = (const float*)d_in[2];
    const float* as1 = (const float*)d_in[3];
    const float* ad1 = (const float*)d_in[4];
    const float* b1  = (const float*)d_in[5];
    const float* W2  = (const float*)d_in[6];
    const float* as2 = (const float*)d_in[7];
    const float* ad2 = (const float*)d_in[8];
    const float* b2  = (const float*)d_in[9];
    float* out = (float*)d_out;

    __half *h1p, *agg1hp, *xhp, *w1hp, *w2hp, *w2lp;
    float *h2p;
    cudaGetSymbolAddress((void**)&h1p,    d_h1h);
    cudaGetSymbolAddress((void**)&agg1hp, d_agg1h);
    cudaGetSymbolAddress((void**)&xhp,    d_xh);
    cudaGetSymbolAddress((void**)&w1hp,   d_w1h);
    cudaGetSymbolAddress((void**)&w2hp,   d_w2h);
    cudaGetSymbolAddress((void**)&w2lp,   d_w2l);
    cudaGetSymbolAddress((void**)&h2p,    d_h2);

    cudaFuncSetAttribute(gemm1_mma, cudaFuncAttributeMaxDynamicSharedMemorySize, 2 * G1_STAGE);
    cudaFuncSetAttribute(gemm2_mma, cudaFuncAttributeMaxDynamicSharedMemorySize, 2 * G2_STAGE);

    // launch order keeps gemm1 in the profiled slot (#4)
    zero_deg_k<<<(N_NODES + 255) / 256, 256>>>();
    convx_k<<<(N_NODES * F_IN / 4 + 255) / 256, 256>>>(x);
    convw1_k<<<(F_IN * HC / 4 + 255) / 256, 256>>>(W1);
    {
        dim3 g(HC / 128, (N_NODES + 127) / 128);
        gemm1_mma<<<g, 256, 2 * G1_STAGE>>>(xhp, w1hp, as1, ad1, h1p, N_NODES);
    }
    convw2_k<<<(HC * OUTD / 2 + 255) / 256, 256>>>(W2);
    hist_k<<<(N_EDGES + 255) / 256, 256>>>(ei);
    scan_k<<<1, 1024>>>();
    scatter_k<<<(N_EDGES + 255) / 256, 256>>>(ei);

    // layer-1 aggregation: ONE pass, all 8 heads per block
    agg1_k<<<N_NODES, 256>>>(b1);

    // layer 2
    gemm2_mma<<<(N_NODES + 127) / 128, 256, 2 * G2_STAGE>>>(agg1hp, w2hp, w2lp, as2, ad2, h2p, N_NODES);
    agg2_k<<<(N_NODES + 7) / 8, 256>>>(out, b2);
}